// round 1
// baseline (speedup 1.0000x reference)
#include <cuda_runtime.h>

#define BATCH 64
#define N     4096
#define NX    128
#define NU    32
#define NY    32

// out layout: y [64,4096,32] at offset 0, x [64,4097,128] at offset 64*4096*32
#define Y_ELEMS ((size_t)BATCH * N * NY)

// ---------------------------------------------------------------------------
// Scan kernel: one CTA per batch, 128 threads. Thread i owns row i of A and B
// in registers. State x lives in shared memory, double-buffered so one
// __syncthreads per step suffices. Writes x_{k+1} to global each step.
// ---------------------------------------------------------------------------
__global__ void __launch_bounds__(NX) scan_kernel(
    const float* __restrict__ d,
    const float* __restrict__ A,
    const float* __restrict__ B,
    float* __restrict__ xout)
{
    __shared__ float xs[2][NX];
    __shared__ float us[2][NU];

    const int b = blockIdx.x;
    const int i = threadIdx.x;

    float a[NX];
    float bb[NU];
#pragma unroll
    for (int j = 0; j < NX; j++) a[j] = A[i * NX + j];
#pragma unroll
    for (int j = 0; j < NU; j++) bb[j] = B[i * NU + j];

    const float* u  = d + (size_t)b * N * NU;          // [N, NU]
    float*       xb = xout + (size_t)b * (N + 1) * NX; // [N+1, NX]

    // x_0 = 0
    xs[0][i] = 0.0f;
    xb[i]    = 0.0f;
    if (i < NU) us[0][i] = u[i];
    __syncthreads();

    int p = 0;
    for (int k = 0; k < N; k++) {
        const float4* x4 = (const float4*)xs[p];
        const float4* u4 = (const float4*)us[p];
        float acc0 = 0.f, acc1 = 0.f, acc2 = 0.f, acc3 = 0.f;
#pragma unroll
        for (int j = 0; j < NX / 4; j++) {
            float4 v = x4[j];
            acc0 += a[4 * j + 0] * v.x;
            acc1 += a[4 * j + 1] * v.y;
            acc2 += a[4 * j + 2] * v.z;
            acc3 += a[4 * j + 3] * v.w;
        }
#pragma unroll
        for (int j = 0; j < NU / 4; j++) {
            float4 v = u4[j];
            acc0 += bb[4 * j + 0] * v.x;
            acc1 += bb[4 * j + 1] * v.y;
            acc2 += bb[4 * j + 2] * v.z;
            acc3 += bb[4 * j + 3] * v.w;
        }
        float x_new = (acc0 + acc1) + (acc2 + acc3);

        // write next-state buffer; prefetch next u; emit x_{k+1}
        xs[p ^ 1][i] = x_new;
        if (i < NU && (k + 1) < N) us[p ^ 1][i] = u[(size_t)(k + 1) * NU + i];
        xb[(size_t)(k + 1) * NX + i] = x_new;
        __syncthreads();
        p ^= 1;
    }
}

// ---------------------------------------------------------------------------
// Output kernel: y[b,k,:] = C x[b,k] + D u[b,k]. Fully parallel.
// Grid: (64 time-chunks, 64 batches). Block: 256 threads = 8 warps.
// Warp w handles timesteps w*8 .. w*8+7 of the chunk; lane = output channel.
// x/u tiles staged in smem (broadcast reads); C,D rows held in registers.
// ---------------------------------------------------------------------------
#define TCHUNK 64

__global__ void __launch_bounds__(256) y_kernel(
    const float* __restrict__ d,
    const float* __restrict__ C,
    const float* __restrict__ D,
    const float* __restrict__ x,
    float* __restrict__ y)
{
    __shared__ float xsh[TCHUNK][NX];   // 32 KB
    __shared__ float ush[TCHUNK][NU];   // 8 KB

    const int chunk = blockIdx.x;  // 0..63
    const int b     = blockIdx.y;  // 0..63
    const int tid   = threadIdx.x;

    // Stage x tile: TCHUNK*NX = 8192 contiguous floats
    {
        const float4* xg4 = (const float4*)(x + (size_t)b * (N + 1) * NX
                                              + (size_t)chunk * TCHUNK * NX);
        float4* xs4 = (float4*)&xsh[0][0];
#pragma unroll
        for (int r = 0; r < (TCHUNK * NX / 4) / 256; r++)
            xs4[tid + 256 * r] = xg4[tid + 256 * r];
    }
    // Stage u tile: TCHUNK*NU = 2048 contiguous floats
    {
        const float4* ug4 = (const float4*)(d + (size_t)b * N * NU
                                              + (size_t)chunk * TCHUNK * NU);
        float4* us4 = (float4*)&ush[0][0];
#pragma unroll
        for (int r = 0; r < (TCHUNK * NU / 4) / 256; r++)
            us4[tid + 256 * r] = ug4[tid + 256 * r];
    }
    __syncthreads();

    const int o = tid & 31;   // output channel
    const int w = tid >> 5;   // warp -> timestep group

    float c[NX], dd[NU];
    {
        const float4* c4 = (const float4*)(C + (size_t)o * NX);
#pragma unroll
        for (int j = 0; j < NX / 4; j++) {
            float4 v = c4[j];
            c[4 * j + 0] = v.x; c[4 * j + 1] = v.y;
            c[4 * j + 2] = v.z; c[4 * j + 3] = v.w;
        }
        const float4* d4 = (const float4*)(D + (size_t)o * NU);
#pragma unroll
        for (int j = 0; j < NU / 4; j++) {
            float4 v = d4[j];
            dd[4 * j + 0] = v.x; dd[4 * j + 1] = v.y;
            dd[4 * j + 2] = v.z; dd[4 * j + 3] = v.w;
        }
    }

    float* yb = y + (size_t)b * N * NY + (size_t)chunk * TCHUNK * NY;

#pragma unroll
    for (int tt = 0; tt < 8; tt++) {
        const int t = w * 8 + tt;
        const float4* xr = (const float4*)xsh[t];
        const float4* ur = (const float4*)ush[t];
        float a0 = 0.f, a1 = 0.f, a2 = 0.f, a3 = 0.f;
#pragma unroll
        for (int j = 0; j < NX / 4; j++) {
            float4 v = xr[j];
            a0 += c[4 * j + 0] * v.x;
            a1 += c[4 * j + 1] * v.y;
            a2 += c[4 * j + 2] * v.z;
            a3 += c[4 * j + 3] * v.w;
        }
#pragma unroll
        for (int j = 0; j < NU / 4; j++) {
            float4 v = ur[j];
            a0 += dd[4 * j + 0] * v.x;
            a1 += dd[4 * j + 1] * v.y;
            a2 += dd[4 * j + 2] * v.z;
            a3 += dd[4 * j + 3] * v.w;
        }
        yb[(size_t)t * NY + o] = (a0 + a1) + (a2 + a3);
    }
}

// ---------------------------------------------------------------------------
extern "C" void kernel_launch(void* const* d_in, const int* in_sizes, int n_in,
                              void* d_out, int out_size)
{
    const float* d = (const float*)d_in[0];  // [64,4096,32,1]
    const float* A = (const float*)d_in[1];  // [128,128]
    const float* B = (const float*)d_in[2];  // [128,32]
    const float* C = (const float*)d_in[3];  // [32,128]
    const float* D = (const float*)d_in[4];  // [32,32]

    float* y = (float*)d_out;                // [64,4096,32]
    float* x = (float*)d_out + Y_ELEMS;      // [64,4097,128]

    // Phase 1: sequential state scan (writes all x, including x_0 = 0)
    scan_kernel<<<BATCH, NX>>>(d, A, B, x);

    // Phase 2: fully parallel output projection
    dim3 grid(N / TCHUNK, BATCH);
    y_kernel<<<grid, 256>>>(d, C, D, x, y);
}

// round 2
// speedup vs baseline: 1.3573x; 1.3573x over previous
#include <cuda_runtime.h>

#define BATCH 64
#define N     4096
#define NX    128
#define NU    32
#define NY    32
#define L     64           // chunk length
#define NCHUNK (N / L)     // 64

#define Y_ELEMS ((size_t)BATCH * N * NY)

// Scratch (no cudaMalloc allowed)
__device__ float g_P0[NX * NX];            // matrix-power ping
__device__ float g_P1[NX * NX];            // matrix-power pong (ends holding A^64)
__device__ float g_XS[BATCH * NCHUNK * NX]; // chunk start states x_{cL}

// ---------------------------------------------------------------------------
// 128x128 matrix square: out = in * in. grid=128 (row), block=128 (col).
// ---------------------------------------------------------------------------
__global__ void __launch_bounds__(NX) matsq(const float* __restrict__ in,
                                            float* __restrict__ out)
{
    __shared__ float row[NX];
    const int r = blockIdx.x, c = threadIdx.x;
    row[c] = in[r * NX + c];
    __syncthreads();
    float acc = 0.f;
#pragma unroll 16
    for (int j = 0; j < NX; j++) acc += row[j] * in[j * NX + c];
    out[r * NX + c] = acc;
}

// ---------------------------------------------------------------------------
// Pass 1: local scans. grid=(NCHUNK, BATCH), block=128.
// Each CTA runs 64 steps from x=0, writing local contributions w_k into
// xout[b][cL+k] for k=1..L.
// ---------------------------------------------------------------------------
__global__ void __launch_bounds__(NX, 2) pass1_local(
    const float* __restrict__ d,
    const float* __restrict__ A,
    const float* __restrict__ B,
    float* __restrict__ xout)
{
    __shared__ float xs[2][NX];
    __shared__ float us[2][NU];

    const int c = blockIdx.x, b = blockIdx.y, i = threadIdx.x;

    float a[NX], bb[NU];
#pragma unroll
    for (int j = 0; j < NX; j++) a[j] = A[i * NX + j];
#pragma unroll
    for (int j = 0; j < NU; j++) bb[j] = B[i * NU + j];

    const float* u  = d + (size_t)b * N * NU + (size_t)c * L * NU;   // [L, NU]
    float*       xb = xout + (size_t)b * (N + 1) * NX + (size_t)c * L * NX;

    if (c == 0 && i < NX) xout[(size_t)b * (N + 1) * NX + i] = 0.0f; // x_0 = 0

    xs[0][i] = 0.0f;
    if (i < NU) us[0][i] = u[i];
    __syncthreads();

    int p = 0;
#pragma unroll 2
    for (int k = 0; k < L; k++) {
        const float4* x4 = (const float4*)xs[p];
        const float4* u4 = (const float4*)us[p];
        float acc0 = 0.f, acc1 = 0.f, acc2 = 0.f, acc3 = 0.f;
#pragma unroll
        for (int j = 0; j < NX / 4; j++) {
            float4 v = x4[j];
            acc0 += a[4 * j + 0] * v.x;
            acc1 += a[4 * j + 1] * v.y;
            acc2 += a[4 * j + 2] * v.z;
            acc3 += a[4 * j + 3] * v.w;
        }
#pragma unroll
        for (int j = 0; j < NU / 4; j++) {
            float4 v = u4[j];
            acc0 += bb[4 * j + 0] * v.x;
            acc1 += bb[4 * j + 1] * v.y;
            acc2 += bb[4 * j + 2] * v.z;
            acc3 += bb[4 * j + 3] * v.w;
        }
        float w = (acc0 + acc1) + (acc2 + acc3);

        xs[p ^ 1][i] = w;
        if (i < NU && (k + 1) < L) us[p ^ 1][i] = u[(size_t)(k + 1) * NU + i];
        xb[(size_t)(k + 1) * NX + i] = w;
        __syncthreads();
        p ^= 1;
    }
}

// ---------------------------------------------------------------------------
// Pass 2: serial combine across chunks. grid=BATCH, block=128.
// x_start[c+1] = A^L * x_start[c] + w_L[c];  w_L[c] = xout[b][(c+1)L].
// Writes x_start[c] for all chunks into g_XS.
// ---------------------------------------------------------------------------
__global__ void __launch_bounds__(NX) pass2_combine(
    const float* __restrict__ A64,
    const float* __restrict__ xout,
    float* __restrict__ XS)
{
    __shared__ float s[NX];
    const int b = blockIdx.x, i = threadIdx.x;

    float a[NX];
#pragma unroll
    for (int j = 0; j < NX; j++) a[j] = A64[i * NX + j];

    const float* xb  = xout + (size_t)b * (N + 1) * NX;
    float*       xsb = XS + (size_t)b * NCHUNK * NX;

    s[i] = 0.f;
    xsb[i] = 0.f;               // x_start[0] = 0
    __syncthreads();

    for (int c = 0; c < NCHUNK - 1; c++) {
        const float4* s4 = (const float4*)s;
        float acc0 = 0.f, acc1 = 0.f, acc2 = 0.f, acc3 = 0.f;
#pragma unroll
        for (int j = 0; j < NX / 4; j++) {
            float4 v = s4[j];
            acc0 += a[4 * j + 0] * v.x;
            acc1 += a[4 * j + 1] * v.y;
            acc2 += a[4 * j + 2] * v.z;
            acc3 += a[4 * j + 3] * v.w;
        }
        float wl = xb[(size_t)(c + 1) * L * NX + i];
        float ns = (acc0 + acc1) + (acc2 + acc3) + wl;
        __syncthreads();
        s[i] = ns;
        xsb[(size_t)(c + 1) * NX + i] = ns;
        __syncthreads();
    }
}

// ---------------------------------------------------------------------------
// Pass 3: parallel correction. grid=(NCHUNK-1, BATCH) with c = blockIdx.x+1.
// p_0 = x_start[c];  p_k = A p_{k-1};  xout[b][cL+k] += p_k, k=1..L.
// (Chunk 0 needs no correction: x_start[0] = 0.)
// ---------------------------------------------------------------------------
__global__ void __launch_bounds__(NX, 2) pass3_fix(
    const float* __restrict__ A,
    const float* __restrict__ XS,
    float* __restrict__ xout)
{
    __shared__ float ps[2][NX];
    const int c = blockIdx.x + 1, b = blockIdx.y, i = threadIdx.x;

    float a[NX];
#pragma unroll
    for (int j = 0; j < NX; j++) a[j] = A[i * NX + j];

    float* xb = xout + (size_t)b * (N + 1) * NX + (size_t)c * L * NX;

    ps[0][i] = XS[((size_t)b * NCHUNK + c) * NX + i];
    __syncthreads();

    float nxt = xb[(size_t)1 * NX + i];   // prefetch slot k=1
    int p = 0;
#pragma unroll 2
    for (int k = 1; k <= L; k++) {
        const float4* p4 = (const float4*)ps[p];
        float acc0 = 0.f, acc1 = 0.f, acc2 = 0.f, acc3 = 0.f;
#pragma unroll
        for (int j = 0; j < NX / 4; j++) {
            float4 v = p4[j];
            acc0 += a[4 * j + 0] * v.x;
            acc1 += a[4 * j + 1] * v.y;
            acc2 += a[4 * j + 2] * v.z;
            acc3 += a[4 * j + 3] * v.w;
        }
        float pn = (acc0 + acc1) + (acc2 + acc3);

        float cur = nxt;
        if (k < L) nxt = xb[(size_t)(k + 1) * NX + i];  // prefetch next slot
        xb[(size_t)k * NX + i] = cur + pn;

        ps[p ^ 1][i] = pn;
        __syncthreads();
        p ^= 1;
    }
}

// ---------------------------------------------------------------------------
// Output kernel: y[b,k,:] = C x[b,k] + D u[b,k] (unchanged from R1).
// ---------------------------------------------------------------------------
#define TCHUNK 64

__global__ void __launch_bounds__(256) y_kernel(
    const float* __restrict__ d,
    const float* __restrict__ C,
    const float* __restrict__ D,
    const float* __restrict__ x,
    float* __restrict__ y)
{
    __shared__ float xsh[TCHUNK][NX];
    __shared__ float ush[TCHUNK][NU];

    const int chunk = blockIdx.x;
    const int b     = blockIdx.y;
    const int tid   = threadIdx.x;

    {
        const float4* xg4 = (const float4*)(x + (size_t)b * (N + 1) * NX
                                              + (size_t)chunk * TCHUNK * NX);
        float4* xs4 = (float4*)&xsh[0][0];
#pragma unroll
        for (int r = 0; r < (TCHUNK * NX / 4) / 256; r++)
            xs4[tid + 256 * r] = xg4[tid + 256 * r];
    }
    {
        const float4* ug4 = (const float4*)(d + (size_t)b * N * NU
                                              + (size_t)chunk * TCHUNK * NU);
        float4* us4 = (float4*)&ush[0][0];
#pragma unroll
        for (int r = 0; r < (TCHUNK * NU / 4) / 256; r++)
            us4[tid + 256 * r] = ug4[tid + 256 * r];
    }
    __syncthreads();

    const int o = tid & 31;
    const int w = tid >> 5;

    float c[NX], dd[NU];
    {
        const float4* c4 = (const float4*)(C + (size_t)o * NX);
#pragma unroll
        for (int j = 0; j < NX / 4; j++) {
            float4 v = c4[j];
            c[4 * j + 0] = v.x; c[4 * j + 1] = v.y;
            c[4 * j + 2] = v.z; c[4 * j + 3] = v.w;
        }
        const float4* d4 = (const float4*)(D + (size_t)o * NU);
#pragma unroll
        for (int j = 0; j < NU / 4; j++) {
            float4 v = d4[j];
            dd[4 * j + 0] = v.x; dd[4 * j + 1] = v.y;
            dd[4 * j + 2] = v.z; dd[4 * j + 3] = v.w;
        }
    }

    float* yb = y + (size_t)b * N * NY + (size_t)chunk * TCHUNK * NY;

#pragma unroll
    for (int tt = 0; tt < 8; tt++) {
        const int t = w * 8 + tt;
        const float4* xr = (const float4*)xsh[t];
        const float4* ur = (const float4*)ush[t];
        float a0 = 0.f, a1 = 0.f, a2 = 0.f, a3 = 0.f;
#pragma unroll
        for (int j = 0; j < NX / 4; j++) {
            float4 v = xr[j];
            a0 += c[4 * j + 0] * v.x;
            a1 += c[4 * j + 1] * v.y;
            a2 += c[4 * j + 2] * v.z;
            a3 += c[4 * j + 3] * v.w;
        }
#pragma unroll
        for (int j = 0; j < NU / 4; j++) {
            float4 v = ur[j];
            a0 += dd[4 * j + 0] * v.x;
            a1 += dd[4 * j + 1] * v.y;
            a2 += dd[4 * j + 2] * v.z;
            a3 += dd[4 * j + 3] * v.w;
        }
        yb[(size_t)t * NY + o] = (a0 + a1) + (a2 + a3);
    }
}

// ---------------------------------------------------------------------------
extern "C" void kernel_launch(void* const* d_in, const int* in_sizes, int n_in,
                              void* d_out, int out_size)
{
    const float* d = (const float*)d_in[0];
    const float* A = (const float*)d_in[1];
    const float* B = (const float*)d_in[2];
    const float* C = (const float*)d_in[3];
    const float* D = (const float*)d_in[4];

    float* y = (float*)d_out;
    float* x = (float*)d_out + Y_ELEMS;

    float* P0;  cudaGetSymbolAddress((void**)&P0, g_P0);
    float* P1;  cudaGetSymbolAddress((void**)&P1, g_P1);
    float* XS;  cudaGetSymbolAddress((void**)&XS, g_XS);

    // A^64 via 6 squarings: A->A2->A4->A8->A16->A32->A64 (ends in P1)
    matsq<<<NX, NX>>>(A,  P0);   // A^2
    matsq<<<NX, NX>>>(P0, P1);   // A^4
    matsq<<<NX, NX>>>(P1, P0);   // A^8
    matsq<<<NX, NX>>>(P0, P1);   // A^16
    matsq<<<NX, NX>>>(P1, P0);   // A^32
    matsq<<<NX, NX>>>(P0, P1);   // A^64

    // Pass 1: local chunk scans (fills x with local contributions w_k)
    {
        dim3 g(NCHUNK, BATCH);
        pass1_local<<<g, NX>>>(d, A, B, x);
    }

    // Pass 2: serial chunk combine -> chunk start states in g_XS
    pass2_combine<<<BATCH, NX>>>(P1, x, XS);

    // Pass 3: parallel correction x[cL+k] += A^k x_start[c]
    {
        dim3 g(NCHUNK - 1, BATCH);
        pass3_fix<<<g, NX>>>(A, XS, x);
    }

    // Output projection
    {
        dim3 g(N / TCHUNK, BATCH);
        y_kernel<<<g, 256>>>(d, C, D, x, y);
    }
}